// round 5
// baseline (speedup 1.0000x reference)
#include <cuda_runtime.h>
#include <cstdint>
#include <math.h>

static constexpr int NB = 4, LSEQ = 2048, DIN = 1024, HDIM = 1024, ODIM = 1024;
static constexpr int MTOT = NB * LSEQ;      // 8192
static constexpr int NQKV = 3 * HDIM;       // 3072

// ---------------- scratch (__device__ globals; no allocation allowed) ------
__device__ __align__(256) int8_t g_x0[(size_t)MTOT * DIN];
__device__ __align__(256) int8_t g_x1[(size_t)MTOT * DIN];
__device__ float g_rx[MTOT];
__device__ float g_Wtf[(size_t)NQKV * DIN];
__device__ __align__(256) int8_t g_W0[(size_t)NQKV * DIN];
__device__ __align__(256) int8_t g_W1[(size_t)NQKV * DIN];
__device__ float g_rW[NQKV];
__device__ float g_bcat[NQKV];
__device__ float g_QKV[(size_t)MTOT * NQKV];           // fp32 Q|K|V, ld 3072
__device__ __align__(256) int8_t g_Q0[(size_t)MTOT * HDIM];
__device__ __align__(256) int8_t g_Q1[(size_t)MTOT * HDIM];
__device__ __align__(256) int8_t g_K0[(size_t)MTOT * HDIM];
__device__ __align__(256) int8_t g_K1[(size_t)MTOT * HDIM];
__device__ float g_rQ[MTOT], g_rK[MTOT];
__device__ float g_Vtf[(size_t)NB * ODIM * LSEQ];      // V^T fp32 [4][1024][2048]
__device__ __align__(256) int8_t g_V0[(size_t)NB * ODIM * LSEQ];
__device__ __align__(256) int8_t g_V1[(size_t)NB * ODIM * LSEQ];
__device__ float g_rV[NB * ODIM];
__device__ float g_S[(size_t)NB * LSEQ * LSEQ];        // fp32 scores
__device__ __align__(256) int8_t g_S0[(size_t)NB * LSEQ * LSEQ];
__device__ __align__(256) int8_t g_S1[(size_t)NB * LSEQ * LSEQ];
__device__ float g_rS[NB * LSEQ];

// ---------------- PTX helpers ----------------------------------------------
__device__ __forceinline__ uint32_t smem_u32(const void* p) {
    uint32_t a;
    asm("{ .reg .u64 t; cvta.to.shared.u64 t, %1; cvt.u32.u64 %0, t; }" : "=r"(a) : "l"(p));
    return a;
}
#define CP16(dst, src) \
    asm volatile("cp.async.cg.shared.global [%0], [%1], 16;" :: "r"(dst), "l"(src))
#define CP_COMMIT() asm volatile("cp.async.commit_group;")
#define CP_WAIT0()  asm volatile("cp.async.wait_group 0;")
#define LDSM4(r, addr) \
    asm volatile("ldmatrix.sync.aligned.m8n8.x4.shared.b16 {%0,%1,%2,%3}, [%4];" \
        : "=r"((r)[0]), "=r"((r)[1]), "=r"((r)[2]), "=r"((r)[3]) : "r"(addr))
#define IMMA(d, a, b0v, b1v) \
    asm volatile("mma.sync.aligned.m16n8k32.row.col.s32.s8.s8.s32 " \
        "{%0,%1,%2,%3}, {%4,%5,%6,%7}, {%8,%9}, {%0,%1,%2,%3};" \
        : "+r"((d)[0]), "+r"((d)[1]), "+r"((d)[2]), "+r"((d)[3]) \
        : "r"((a)[0]), "r"((a)[1]), "r"((a)[2]), "r"((a)[3]), "r"(b0v), "r"(b1v))

// ---------------- smem layout: CTA tile 128x64, K-chunk 64 ------------------
// Regions per stage: A0(128x80B) A1 B0(64x80B) B1 -> 30720 B/stage, 2 stages.
static constexpr uint32_t R_A0 = 0, R_A1 = 10240, R_B0 = 20480, R_B1 = 25600;
static constexpr uint32_t STG = 30720;
static constexpr uint32_t SMEM_GEMM = 2 * STG;  // 61440

// ---------------------------------------------------------------------------
// int8 2-limb split GEMM: C[M,N] = mult * (A·B^T) (+ bias[col])
//   A(int8 limbs, per-row scale rsA), B(int8 limbs [N,K], per-row scale rsB)
//   value = rs * (L0*128 + L1);  C = rsA*rsB*(16384*C00 + 128*(C01+C10))
// CTA tile 128x64, warps 4(m)x2(n) -> warp tile 32x32. Persistent grid.
// ---------------------------------------------------------------------------
template <bool BIAS>
__global__ __launch_bounds__(256, 2)
void gemm_i8(const int8_t* __restrict__ A0g, const int8_t* __restrict__ A1g,
             const int8_t* __restrict__ B0g, const int8_t* __restrict__ B1g,
             const float* __restrict__ rsA, const float* __restrict__ rsB,
             const float* __restrict__ bias, float* __restrict__ C,
             int K, int ldc, float mult,
             size_t sA, size_t sB, size_t sC, int sRA, int sRB,
             int gx, int gy, int gz)
{
    extern __shared__ char smem[];
    const uint32_t sq = smem_u32(smem);
    const int t = threadIdx.x, lane = t & 31, wid = t >> 5;
    const int wm = wid & 3, wn = wid >> 2;
    const int NST = K >> 6;
    const int ntiles = gx * gy * gz;

    // ldmatrix offsets
    const uint32_t aoff = (uint32_t)((wm * 32 + (lane & 15)) * 80 + (lane >> 4) * 16);
    const uint32_t boff = (uint32_t)((wn * 32 + (lane & 7) + ((lane >> 4) << 3)) * 80
                                     + (((lane >> 3) & 1) << 4));
    // cp.async smem dst offset (row = t>>2, 16B chunk = t&3)
    const uint32_t dsto = (uint32_t)((t >> 2) * 80 + (t & 3) * 16);
    const int grow = t >> 2, gk16 = (t & 3) * 16;

    for (int tile = blockIdx.x; tile < ntiles; tile += gridDim.x) {
        const int bn = (tile % gx) * 64;
        const int tyz = tile / gx;
        const int bm = (tyz % gy) * 128;
        const int z = tyz / gy;

        const int8_t* pA0 = A0g + (size_t)z * sA;
        const int8_t* pA1 = A1g + (size_t)z * sA;
        const int8_t* pB0 = B0g + (size_t)z * sB;
        const int8_t* pB1 = B1g + (size_t)z * sB;

        auto issue = [&](int s) {
            const uint32_t sb = sq + (uint32_t)(s & 1) * STG;
            const size_t ks = (size_t)s * 64 + gk16;
            CP16(sb + R_A0 + dsto,        pA0 + (size_t)(bm + grow) * K + ks);
            CP16(sb + R_A0 + dsto + 5120, pA0 + (size_t)(bm + 64 + grow) * K + ks);
            CP16(sb + R_A1 + dsto,        pA1 + (size_t)(bm + grow) * K + ks);
            CP16(sb + R_A1 + dsto + 5120, pA1 + (size_t)(bm + 64 + grow) * K + ks);
            CP16(sb + R_B0 + dsto,        pB0 + (size_t)(bn + grow) * K + ks);
            CP16(sb + R_B1 + dsto,        pB1 + (size_t)(bn + grow) * K + ks);
        };

        int c00[2][4][4], cm[2][4][4];
#pragma unroll
        for (int mi = 0; mi < 2; mi++)
#pragma unroll
            for (int ni = 0; ni < 4; ni++)
#pragma unroll
                for (int r = 0; r < 4; r++) { c00[mi][ni][r] = 0; cm[mi][ni][r] = 0; }

        issue(0); CP_COMMIT();

        for (int it = 0; it < NST; ++it) {
            CP_WAIT0();
            __syncthreads();
            if (it + 1 < NST) { issue(it + 1); CP_COMMIT(); }

            const uint32_t sb = sq + (uint32_t)(it & 1) * STG;
#pragma unroll
            for (int s = 0; s < 2; ++s) {       // two k32 steps
                uint32_t a0[2][4], a1[2][4], b0[2][4], b1[2][4];
#pragma unroll
                for (int mi = 0; mi < 2; ++mi) {
                    LDSM4(a0[mi], sb + R_A0 + aoff + mi * 1280u + s * 32u);
                    LDSM4(a1[mi], sb + R_A1 + aoff + mi * 1280u + s * 32u);
                }
#pragma unroll
                for (int p = 0; p < 2; ++p) {
                    LDSM4(b0[p], sb + R_B0 + boff + p * 1280u + s * 32u);
                    LDSM4(b1[p], sb + R_B1 + boff + p * 1280u + s * 32u);
                }
                // pass 1: A0*B0 -> c00
#pragma unroll
                for (int mi = 0; mi < 2; ++mi)
#pragma unroll
                    for (int ni = 0; ni < 4; ++ni)
                        IMMA(c00[mi][ni], a0[mi], b0[ni >> 1][(ni & 1) * 2], b0[ni >> 1][(ni & 1) * 2 + 1]);
                // pass 2: A0*B1 -> cm
#pragma unroll
                for (int mi = 0; mi < 2; ++mi)
#pragma unroll
                    for (int ni = 0; ni < 4; ++ni)
                        IMMA(cm[mi][ni], a0[mi], b1[ni >> 1][(ni & 1) * 2], b1[ni >> 1][(ni & 1) * 2 + 1]);
                // pass 3: A1*B0 -> cm
#pragma unroll
                for (int mi = 0; mi < 2; ++mi)
#pragma unroll
                    for (int ni = 0; ni < 4; ++ni)
                        IMMA(cm[mi][ni], a1[mi], b0[ni >> 1][(ni & 1) * 2], b0[ni >> 1][(ni & 1) * 2 + 1]);
            }
        }

        // ---- epilogue: C = (16384*C00 + 128*Cm) * rsA[row]*mult * rsB[col] (+bias)
        const int lr = lane >> 2, lc = (lane & 3) * 2;
#pragma unroll
        for (int mi = 0; mi < 2; ++mi) {
#pragma unroll
            for (int rp = 0; rp < 2; ++rp) {
                const int row = bm + wm * 32 + mi * 16 + rp * 8 + lr;
                const float sam = rsA[z * sRA + row] * mult;
                float* crow = C + (size_t)z * sC + (size_t)row * ldc;
#pragma unroll
                for (int ni = 0; ni < 4; ++ni) {
                    const int col = bn + wn * 32 + ni * 8 + lc;
                    const float sb0 = rsB[z * sRB + col], sb1 = rsB[z * sRB + col + 1];
                    float f0 = fmaf(16384.f, (float)c00[mi][ni][rp * 2],
                                    128.f * (float)cm[mi][ni][rp * 2]) * sam * sb0;
                    float f1 = fmaf(16384.f, (float)c00[mi][ni][rp * 2 + 1],
                                    128.f * (float)cm[mi][ni][rp * 2 + 1]) * sam * sb1;
                    if (BIAS) { f0 += bias[col]; f1 += bias[col + 1]; }
                    *(float2*)(crow + col) = make_float2(f0, f1);
                }
            }
        }
    }
}

// ---------------------------------------------------------------------------
// Per-row quantization to 2 int8 limbs (14-bit): q = rint(a*16256/rowmax),
// L0 = (q+64)>>7 in [-127,127], L1 = q - 128*L0 in [-64,63].
// KW = float4 loads per thread (Kc = KW*1024).
// ---------------------------------------------------------------------------
template <int KW>
__global__ __launch_bounds__(256)
void quant_rows(const float* __restrict__ in, int ldin,
                int8_t* __restrict__ q0, int8_t* __restrict__ q1,
                float* __restrict__ rrec, int Kc)
{
    const size_t row = blockIdx.x;
    const float* p = in + row * (size_t)ldin;
    const int t = threadIdx.x;
    float4 v[KW];
    float mx = 0.f;
#pragma unroll
    for (int w = 0; w < KW; w++) {
        v[w] = ((const float4*)p)[t + w * 256];
        mx = fmaxf(mx, fmaxf(fmaxf(fabsf(v[w].x), fabsf(v[w].y)),
                             fmaxf(fabsf(v[w].z), fabsf(v[w].w))));
    }
    __shared__ float red[8];
#pragma unroll
    for (int o = 16; o > 0; o >>= 1) mx = fmaxf(mx, __shfl_xor_sync(0xFFFFFFFFu, mx, o));
    if ((t & 31) == 0) red[t >> 5] = mx;
    __syncthreads();
    mx = red[0];
#pragma unroll
    for (int i = 1; i < 8; i++) mx = fmaxf(mx, red[i]);
    mx = fmaxf(mx, 1e-20f);
    const float s = 16256.f / mx;
    if (t == 0) rrec[row] = mx * (1.f / 16256.f);

#pragma unroll
    for (int w = 0; w < KW; w++) {
        int qx = (int)rintf(v[w].x * s), qy = (int)rintf(v[w].y * s);
        int qz = (int)rintf(v[w].z * s), qw = (int)rintf(v[w].w * s);
        int ax = (qx + 64) >> 7, ay = (qy + 64) >> 7, az = (qz + 64) >> 7, aw = (qw + 64) >> 7;
        char4 h = make_char4((char)ax, (char)ay, (char)az, (char)aw);
        char4 l = make_char4((char)(qx - (ax << 7)), (char)(qy - (ay << 7)),
                             (char)(qz - (az << 7)), (char)(qw - (aw << 7)));
        ((char4*)(q0 + row * (size_t)Kc))[t + w * 256] = h;
        ((char4*)(q1 + row * (size_t)Kc))[t + w * 256] = l;
    }
}

// ---------------------------------------------------------------------------
// Transpose Wq/Wk/Wv (z-selected) [D,H] -> Wtf rows [3H, D] fp32.
__global__ __launch_bounds__(256)
void transpose_w(const float* __restrict__ Wq, const float* __restrict__ Wk,
                 const float* __restrict__ Wv, float* __restrict__ out)
{
    __shared__ float tb[32][33];
    const int z = blockIdx.z;
    const float* in = z == 0 ? Wq : (z == 1 ? Wk : Wv);
    float* o = out + (size_t)z * HDIM * DIN;
    const int bx = blockIdx.x * 32, by = blockIdx.y * 32;   // bx: H cols, by: D rows
    const int tx = threadIdx.x & 31, ty = threadIdx.x >> 5;
#pragma unroll
    for (int j = 0; j < 4; j++) {
        int r = ty + j * 8;
        tb[r][tx] = in[(size_t)(by + r) * HDIM + bx + tx];
    }
    __syncthreads();
#pragma unroll
    for (int j = 0; j < 4; j++) {
        int r = ty + j * 8;
        o[(size_t)(bx + r) * DIN + by + tx] = tb[tx][r];
    }
}

// Transpose V segment of QKV: [L,1024] (ld 3072) -> Vtf [1024, L] per batch.
__global__ __launch_bounds__(256)
void transpose_v(const float* __restrict__ QKV, float* __restrict__ out)
{
    __shared__ float tb[32][33];
    const int z = blockIdx.z;
    const float* in = QKV + (size_t)z * LSEQ * NQKV + 2048;
    float* o = out + (size_t)z * ODIM * LSEQ;
    const int bx = blockIdx.x * 32, by = blockIdx.y * 32;   // bx: O cols, by: L rows
    const int tx = threadIdx.x & 31, ty = threadIdx.x >> 5;
#pragma unroll
    for (int j = 0; j < 4; j++) {
        int r = ty + j * 8;
        tb[r][tx] = in[(size_t)(by + r) * NQKV + bx + tx];
    }
    __syncthreads();
#pragma unroll
    for (int j = 0; j < 4; j++) {
        int r = ty + j * 8;
        o[(size_t)(bx + r) * LSEQ + by + tx] = tb[tx][r];
    }
}

__global__ void concat_bias(const float* __restrict__ a, const float* __restrict__ b,
                            const float* __restrict__ c, float* __restrict__ o)
{
    int i = blockIdx.x * 256 + threadIdx.x;
    if (i < 1024) o[i] = a[i];
    else if (i < 2048) o[i] = b[i - 1024];
    else if (i < 3072) o[i] = c[i - 2048];
}

// ---------------------------------------------------------------------------
// Softmax over 2048 cols fused with int8 2-limb quantization.
// Row max of softmax output is exactly inv (= 1/sum), so q = rint(expval*16256).
__global__ __launch_bounds__(256)
void softmax_quant(const float* __restrict__ S, int8_t* __restrict__ q0,
                   int8_t* __restrict__ q1, float* __restrict__ rrec)
{
    const size_t row = blockIdx.x;
    const float* p = S + row * (size_t)LSEQ;
    const int t = threadIdx.x;
    float v[8];
    float m = -1e30f;
#pragma unroll
    for (int i = 0; i < 8; i++) { v[i] = p[t + i * 256]; m = fmaxf(m, v[i]); }
    __shared__ float redm[8], reds[8];
#pragma unroll
    for (int o = 16; o > 0; o >>= 1) m = fmaxf(m, __shfl_xor_sync(0xFFFFFFFFu, m, o));
    if ((t & 31) == 0) redm[t >> 5] = m;
    __syncthreads();
    m = redm[0];
#pragma unroll
    for (int i = 1; i < 8; i++) m = fmaxf(m, redm[i]);
    float s = 0.0f;
#pragma unroll
    for (int i = 0; i < 8; i++) { v[i] = __expf(v[i] - m); s += v[i]; }
#pragma unroll
    for (int o = 16; o > 0; o >>= 1) s += __shfl_xor_sync(0xFFFFFFFFu, s, o);
    if ((t & 31) == 0) reds[t >> 5] = s;
    __syncthreads();
    s = reds[0];
#pragma unroll
    for (int i = 1; i < 8; i++) s += reds[i];
    const float inv = 1.0f / s;
    if (t == 0) rrec[row] = inv * (1.f / 16256.f);
    int8_t* p0 = q0 + row * (size_t)LSEQ;
    int8_t* p1 = q1 + row * (size_t)LSEQ;
#pragma unroll
    for (int i = 0; i < 8; i++) {
        int q = (int)rintf(v[i] * 16256.f);
        int a0 = (q + 64) >> 7;
        p0[t + i * 256] = (int8_t)a0;
        p1[t + i * 256] = (int8_t)(q - (a0 << 7));
    }
}

// ---------------------------------------------------------------------------
extern "C" void kernel_launch(void* const* d_in, const int* in_sizes, int n_in,
                              void* d_out, int out_size)
{
    const float* x  = (const float*)d_in[0];
    const float* Wq = (const float*)d_in[1];
    const float* bq = (const float*)d_in[2];
    const float* Wk = (const float*)d_in[3];
    const float* bk = (const float*)d_in[4];
    const float* Wv = (const float*)d_in[5];
    const float* bv = (const float*)d_in[6];
    float* out = (float*)d_out;

    int8_t *x0, *x1, *W0, *W1, *Q0, *Q1, *K0, *K1, *V0, *V1, *S0, *S1;
    float *rx, *rW, *rQ, *rK, *rV, *rS, *Wtf, *QKV, *Vtf, *S, *bcat;
    cudaGetSymbolAddress((void**)&x0, g_x0);  cudaGetSymbolAddress((void**)&x1, g_x1);
    cudaGetSymbolAddress((void**)&rx, g_rx);
    cudaGetSymbolAddress((void**)&Wtf, g_Wtf);
    cudaGetSymbolAddress((void**)&W0, g_W0);  cudaGetSymbolAddress((void**)&W1, g_W1);
    cudaGetSymbolAddress((void**)&rW, g_rW);  cudaGetSymbolAddress((void**)&bcat, g_bcat);
    cudaGetSymbolAddress((void**)&QKV, g_QKV);
    cudaGetSymbolAddress((void**)&Q0, g_Q0);  cudaGetSymbolAddress((void**)&Q1, g_Q1);
    cudaGetSymbolAddress((void**)&K0, g_K0);  cudaGetSymbolAddress((void**)&K1, g_K1);
    cudaGetSymbolAddress((void**)&rQ, g_rQ);  cudaGetSymbolAddress((void**)&rK, g_rK);
    cudaGetSymbolAddress((void**)&Vtf, g_Vtf);
    cudaGetSymbolAddress((void**)&V0, g_V0);  cudaGetSymbolAddress((void**)&V1, g_V1);
    cudaGetSymbolAddress((void**)&rV, g_rV);
    cudaGetSymbolAddress((void**)&S, g_S);
    cudaGetSymbolAddress((void**)&S0, g_S0);  cudaGetSymbolAddress((void**)&S1, g_S1);
    cudaGetSymbolAddress((void**)&rS, g_rS);

    cudaFuncSetAttribute(gemm_i8<true>,  cudaFuncAttributeMaxDynamicSharedMemorySize, SMEM_GEMM);
    cudaFuncSetAttribute(gemm_i8<false>, cudaFuncAttributeMaxDynamicSharedMemorySize, SMEM_GEMM);

    const int PGRID = 296;

    // 1) quantize x (per-row), transpose+quantize weights, concat bias
    quant_rows<1><<<MTOT, 256>>>(x, DIN, x0, x1, rx, DIN);
    transpose_w<<<dim3(HDIM / 32, DIN / 32, 3), 256>>>(Wq, Wk, Wv, Wtf);
    quant_rows<1><<<NQKV, 256>>>(Wtf, DIN, W0, W1, rW, DIN);
    concat_bias<<<12, 256>>>(bq, bk, bv, bcat);

    // 2) merged QKV projection -> fp32 QKV [8192 x 3072]
    gemm_i8<true><<<PGRID, 256, SMEM_GEMM>>>(
        x0, x1, W0, W1, rx, rW, bcat, QKV,
        DIN, NQKV, 1.0f, 0, 0, 0, 0, 0,
        NQKV / 64, MTOT / 128, 1);

    // 3) quantize Q, K rows; transpose + quantize V
    quant_rows<1><<<MTOT, 256>>>(QKV, NQKV, Q0, Q1, rQ, HDIM);
    quant_rows<1><<<MTOT, 256>>>(QKV + 1024, NQKV, K0, K1, rK, HDIM);
    transpose_v<<<dim3(ODIM / 32, LSEQ / 32, NB), 256>>>(QKV, Vtf);
    quant_rows<2><<<NB * ODIM, 256>>>(Vtf, LSEQ, V0, V1, rV, LSEQ);

    // 4) S = (Q @ K^T) / sqrt(L), batched
    gemm_i8<false><<<PGRID, 256, SMEM_GEMM>>>(
        Q0, Q1, K0, K1, rQ, rK, nullptr, S,
        HDIM, LSEQ, rsqrtf((float)LSEQ),
        (size_t)LSEQ * HDIM, (size_t)LSEQ * HDIM, (size_t)LSEQ * LSEQ,
        LSEQ, LSEQ,
        LSEQ / 64, LSEQ / 128, NB);

    // 5) softmax + quantize S
    softmax_quant<<<NB * LSEQ, 256>>>(S, S0, S1, rS);

    // 6) out = S @ V^T, batched
    gemm_i8<false><<<PGRID, 256, SMEM_GEMM>>>(
        S0, S1, V0, V1, rS, rV, nullptr, out,
        LSEQ, ODIM, 1.0f,
        (size_t)LSEQ * LSEQ, (size_t)ODIM * LSEQ, (size_t)LSEQ * ODIM,
        LSEQ, ODIM,
        ODIM / 64, LSEQ / 128, NB);
}

// round 6
// speedup vs baseline: 1.2441x; 1.2441x over previous
#include <cuda_runtime.h>
#include <cuda_bf16.h>
#include <cstdint>
#include <math.h>

static constexpr int NB = 4, LSEQ = 2048, DIN = 1024, HDIM = 1024, ODIM = 1024;
static constexpr int MTOT = NB * LSEQ; // 8192
static constexpr int NQKV = 3 * HDIM;  // 3072

// ---------------- scratch (__device__ globals) ------------------------------
__device__ __nv_bfloat16 g_xh[(size_t)MTOT * DIN];
__device__ __nv_bfloat16 g_xl[(size_t)MTOT * DIN];
__device__ float g_Wtf[(size_t)NQKV * DIN];
__device__ __nv_bfloat16 g_Wth[(size_t)NQKV * DIN];
__device__ __nv_bfloat16 g_Wtl[(size_t)NQKV * DIN];
__device__ float g_bcat[NQKV];
__device__ float g_Qf[(size_t)MTOT * HDIM];
__device__ float g_Kf[(size_t)MTOT * HDIM];
__device__ float g_Vf[(size_t)MTOT * ODIM];
__device__ __nv_bfloat16 g_Qh[(size_t)MTOT * HDIM];
__device__ __nv_bfloat16 g_Ql[(size_t)MTOT * HDIM];
__device__ __nv_bfloat16 g_Kh[(size_t)MTOT * HDIM];
__device__ __nv_bfloat16 g_Kl[(size_t)MTOT * HDIM];
__device__ float g_Vtf[(size_t)NB * ODIM * LSEQ];
__device__ __nv_bfloat16 g_Vth[(size_t)NB * ODIM * LSEQ];
__device__ __nv_bfloat16 g_Vtl[(size_t)NB * ODIM * LSEQ];
__device__ float g_S[(size_t)NB * LSEQ * LSEQ];
__device__ __nv_bfloat16 g_Sh[(size_t)NB * LSEQ * LSEQ];
__device__ __nv_bfloat16 g_Sl[(size_t)NB * LSEQ * LSEQ];

// ---------------- PTX helpers ----------------------------------------------
__device__ __forceinline__ uint32_t smem_u32(const void* p) {
    uint32_t a;
    asm("{ .reg .u64 t; cvta.to.shared.u64 t, %1; cvt.u32.u64 %0, t; }" : "=r"(a) : "l"(p));
    return a;
}
#define CP16(dst, src) \
    asm volatile("cp.async.cg.shared.global [%0], [%1], 16;" :: "r"(dst), "l"(src))
#define CP_COMMIT() asm volatile("cp.async.commit_group;")
#define CP_WAIT0()  asm volatile("cp.async.wait_group 0;")
#define LDSM4(r, addr) \
    asm volatile("ldmatrix.sync.aligned.m8n8.x4.shared.b16 {%0,%1,%2,%3}, [%4];" \
        : "=r"((r)[0]), "=r"((r)[1]), "=r"((r)[2]), "=r"((r)[3]) : "r"(addr))
#define MMA16816(d, a, b0v, b1v) \
    asm volatile("mma.sync.aligned.m16n8k16.row.col.f32.bf16.bf16.f32 " \
        "{%0,%1,%2,%3}, {%4,%5,%6,%7}, {%8,%9}, {%0,%1,%2,%3};" \
        : "+f"((d)[0]), "+f"((d)[1]), "+f"((d)[2]), "+f"((d)[3]) \
        : "r"((a)[0]), "r"((a)[1]), "r"((a)[2]), "r"((a)[3]), "r"(b0v), "r"(b1v))

static constexpr uint32_t OP_BYTES = 128 * 80;          // one operand per stage
static constexpr uint32_t STAGE_BYTES = 4 * OP_BYTES;   // Ah|Al|Bh|Bl
static constexpr uint32_t SMEM_HYB = 2 * STAGE_BYTES;   // 81920
static constexpr int T_CTAS = 148;

// ---------------- epilogue store (pair) --------------------------------------
// EPI 0: plain fp32 C. EPI 1: QKV segment split (Qf/Kf/Vf + Q/K limbs).
template <int EPI>
__device__ __forceinline__ void epi_store2(
    float v0, float v1, int row, int col,
    float* __restrict__ Cf, int ldc, size_t zCoff,
    float* __restrict__ Qf, float* __restrict__ Kf, float* __restrict__ Vf,
    __nv_bfloat16* __restrict__ Qh, __nv_bfloat16* __restrict__ Ql,
    __nv_bfloat16* __restrict__ Kh, __nv_bfloat16* __restrict__ Kl)
{
    if (EPI == 0) {
        *(float2*)(Cf + zCoff + (size_t)row * ldc + col) = make_float2(v0, v1);
    } else {
        const int seg = col >> 10, lc = col & 1023;
        const size_t o = (size_t)row * 1024 + lc;
        if (seg == 2) {
            *(float2*)(Vf + o) = make_float2(v0, v1);
        } else {
            float* F = seg ? Kf : Qf;
            __nv_bfloat16* H = seg ? Kh : Qh;
            __nv_bfloat16* L = seg ? Kl : Ql;
            *(float2*)(F + o) = make_float2(v0, v1);
            __nv_bfloat162 h = __floats2bfloat162_rn(v0, v1);
            __nv_bfloat162 l = __floats2bfloat162_rn(v0 - __bfloat162float(h.x),
                                                     v1 - __bfloat162float(h.y));
            *(__nv_bfloat162*)(H + o) = h;
            *(__nv_bfloat162*)(L + o) = l;
        }
    }
}

// ---------------------------------------------------------------------------
// Hybrid GEMM: C[M,N] = scale*(A[M,K] @ B[N,K]^T) (+bias[col]).
// CTAs 0..147: tensor path (bf16 hi/lo 3-pass, tiles [0,ntT)).
// CTAs 148..295: fp32 FMA path (exact, tiles [ntT, ntiles)).
// One of each per SM -> tensor pipe + FMA pipe run concurrently.
// ---------------------------------------------------------------------------
template <int EPI, bool BIAS>
__global__ __launch_bounds__(256, 2)
void gemm_hybrid(const float* __restrict__ Af,
                 const __nv_bfloat16* __restrict__ Ah, const __nv_bfloat16* __restrict__ Al,
                 const float* __restrict__ Bf,
                 const __nv_bfloat16* __restrict__ Bh, const __nv_bfloat16* __restrict__ Bl,
                 const float* __restrict__ bias, float scale, int K, int lda, int ldb,
                 size_t zA, size_t zB,
                 float* __restrict__ Cf, int ldc, size_t zC,
                 float* __restrict__ Qf, float* __restrict__ Kf, float* __restrict__ Vf,
                 __nv_bfloat16* __restrict__ Qh, __nv_bfloat16* __restrict__ Ql,
                 __nv_bfloat16* __restrict__ Kh, __nv_bfloat16* __restrict__ Kl,
                 int gx, int gy, int gz, int ntT)
{
    extern __shared__ char smem[];
    const int bid = blockIdx.x;
    const int t = threadIdx.x, lane = t & 31, wid = t >> 5;
    const int ntiles = gx * gy * gz;

    if (bid < T_CTAS) {
        // ================= TENSOR PATH =================
        const uint32_t sq = smem_u32(smem);
        const int NST = K >> 5;
        const int m0w = (wid & 1) * 64, n0w = (wid >> 1) * 32;
        const uint32_t aoff = (uint32_t)((m0w + (lane & 15)) * 80 + (lane >> 4) * 16);
        const uint32_t boff = (uint32_t)((n0w + (lane & 15)) * 80 + (lane >> 4) * 16);
        const uint32_t dsto = (uint32_t)((t >> 2) * 80 + (t & 3) * 16);

        for (int tile = bid; tile < ntT; tile += T_CTAS) {
            const int bn = (tile % gx) * 128;
            const int tyz = tile / gx;
            const int bm = (tyz % gy) * 128;
            const int z = tyz / gy;

            const char* gAh = (const char*)(Ah + z * zA + (size_t)(bm + (t >> 2)) * lda + (t & 3) * 8);
            const char* gAl = (const char*)(Al + z * zA + (size_t)(bm + (t >> 2)) * lda + (t & 3) * 8);
            const char* gBh = (const char*)(Bh + z * zB + (size_t)(bn + (t >> 2)) * ldb + (t & 3) * 8);
            const char* gBl = (const char*)(Bl + z * zB + (size_t)(bn + (t >> 2)) * ldb + (t & 3) * 8);
            const size_t rA = (size_t)64 * lda * 2, rB = (size_t)64 * ldb * 2;

            auto issue = [&](int s) {
                uint32_t sb = sq + (uint32_t)(s & 1) * STAGE_BYTES;
                size_t ko = (size_t)s * 64;
                CP16(sb + dsto,                      gAh + ko);
                CP16(sb + dsto + 5120,               gAh + rA + ko);
                CP16(sb + OP_BYTES + dsto,           gAl + ko);
                CP16(sb + OP_BYTES + dsto + 5120,    gAl + rA + ko);
                CP16(sb + 2*OP_BYTES + dsto,         gBh + ko);
                CP16(sb + 2*OP_BYTES + dsto + 5120,  gBh + rB + ko);
                CP16(sb + 3*OP_BYTES + dsto,         gBl + ko);
                CP16(sb + 3*OP_BYTES + dsto + 5120,  gBl + rB + ko);
            };

            float acc[4][4][4];
#pragma unroll
            for (int i = 0; i < 4; i++)
#pragma unroll
                for (int j = 0; j < 4; j++)
#pragma unroll
                    for (int r = 0; r < 4; r++) acc[i][j][r] = 0.0f;

            issue(0); CP_COMMIT();

            for (int it = 0; it < NST; ++it) {
                CP_WAIT0();
                __syncthreads();
                if (it + 1 < NST) { issue(it + 1); CP_COMMIT(); }

                const uint32_t sb = sq + (uint32_t)(it & 1) * STAGE_BYTES;
#pragma unroll
                for (int s = 0; s < 2; ++s) {
                    uint32_t ah[4][4], bh[2][4], bl[2][4];
#pragma unroll
                    for (int tm = 0; tm < 4; ++tm)
                        LDSM4(ah[tm], sb + aoff + tm * 1280u + s * 32u);
#pragma unroll
                    for (int tn = 0; tn < 2; ++tn) {
                        LDSM4(bh[tn], sb + 2*OP_BYTES + boff + tn * 1280u + s * 32u);
                        LDSM4(bl[tn], sb + 3*OP_BYTES + boff + tn * 1280u + s * 32u);
                    }
#pragma unroll
                    for (int mi = 0; mi < 4; ++mi)
#pragma unroll
                        for (int ni = 0; ni < 4; ++ni)
                            MMA16816(acc[mi][ni], ah[mi], bh[ni >> 1][ni & 1], bh[ni >> 1][2 + (ni & 1)]);
#pragma unroll
                    for (int mi = 0; mi < 4; ++mi)
#pragma unroll
                        for (int ni = 0; ni < 4; ++ni)
                            MMA16816(acc[mi][ni], ah[mi], bl[ni >> 1][ni & 1], bl[ni >> 1][2 + (ni & 1)]);
                    uint32_t al[4][4];
#pragma unroll
                    for (int tm = 0; tm < 4; ++tm)
                        LDSM4(al[tm], sb + OP_BYTES + aoff + tm * 1280u + s * 32u);
#pragma unroll
                    for (int mi = 0; mi < 4; ++mi)
#pragma unroll
                        for (int ni = 0; ni < 4; ++ni)
                            MMA16816(acc[mi][ni], al[mi], bh[ni >> 1][ni & 1], bh[ni >> 1][2 + (ni & 1)]);
                }
            }

            const int lr = lane >> 2, lc = (lane & 3) * 2;
            const size_t zCoff = (size_t)z * zC;
#pragma unroll
            for (int mi = 0; mi < 4; ++mi) {
                const int r0 = bm + m0w + mi * 16 + lr;
#pragma unroll
                for (int ni = 0; ni < 4; ++ni) {
                    const int col = bn + n0w + ni * 8 + lc;
                    float b0 = 0.f, b1 = 0.f;
                    if (BIAS) { b0 = bias[col]; b1 = bias[col + 1]; }
                    epi_store2<EPI>(acc[mi][ni][0] * scale + b0, acc[mi][ni][1] * scale + b1,
                                    r0, col, Cf, ldc, zCoff, Qf, Kf, Vf, Qh, Ql, Kh, Kl);
                    epi_store2<EPI>(acc[mi][ni][2] * scale + b0, acc[mi][ni][3] * scale + b1,
                                    r0 + 8, col, Cf, ldc, zCoff, Qf, Kf, Vf, Qh, Ql, Kh, Kl);
                }
            }
        }
    } else {
        // ================= FMA PATH (exact fp32) =================
        float* sA = (float*)smem;          // [16][128]
        float* sB = sA + 16 * 128;         // [16][128]
        const int tx = t & 15, ty = t >> 4;

        for (int tile = ntT + (bid - T_CTAS); tile < ntiles; tile += T_CTAS) {
            const int bn = (tile % gx) * 128;
            const int tyz = tile / gx;
            const int bm = (tyz % gy) * 128;
            const int z = tyz / gy;
            const float* Ab = Af + (size_t)z * zA;
            const float* Bb = Bf + (size_t)z * zB;

            float acc[8][8];
#pragma unroll
            for (int i = 0; i < 8; i++)
#pragma unroll
                for (int j = 0; j < 8; j++) acc[i][j] = 0.0f;

            for (int k0 = 0; k0 < K; k0 += 16) {
#pragma unroll
                for (int s2 = 0; s2 < 2; s2++) {
                    int s = t + s2 * 256;
                    int row = s >> 2, kq = (s & 3) * 4;
                    float4 v = *(const float4*)(Ab + (size_t)(bm + row) * lda + k0 + kq);
                    sA[(kq + 0) * 128 + row] = v.x;
                    sA[(kq + 1) * 128 + row] = v.y;
                    sA[(kq + 2) * 128 + row] = v.z;
                    sA[(kq + 3) * 128 + row] = v.w;
                }
#pragma unroll
                for (int s2 = 0; s2 < 2; s2++) {
                    int s = t + s2 * 256;
                    int row = s >> 2, kq = (s & 3) * 4;
                    float4 v = *(const float4*)(Bb + (size_t)(bn + row) * ldb + k0 + kq);
                    sB[(kq + 0) * 128 + row] = v.x;
                    sB[(kq + 1) * 128 + row] = v.y;
                    sB[(kq + 2) * 128 + row] = v.z;
                    sB[(kq + 3) * 128 + row] = v.w;
                }
                __syncthreads();
#pragma unroll
                for (int kk = 0; kk < 16; kk++) {
                    float4 a0 = *(const float4*)&sA[kk * 128 + ty * 4];
                    float4 a1 = *(const float4*)&sA[kk * 128 + 64 + ty * 4];
                    float4 b0 = *(const float4*)&sB[kk * 128 + tx * 4];
                    float4 b1 = *(const float4*)&sB[kk * 128 + 64 + tx * 4];
                    float a[8] = {a0.x, a0.y, a0.z, a0.w, a1.x, a1.y, a1.z, a1.w};
                    float b[8] = {b0.x, b0.y, b0.z, b0.w, b1.x, b1.y, b1.z, b1.w};
#pragma unroll
                    for (int i = 0; i < 8; i++)
#pragma unroll
                        for (int j = 0; j < 8; j++)
                            acc[i][j] = fmaf(a[i], b[j], acc[i][j]);
                }
                __syncthreads();
            }

            const size_t zCoff = (size_t)z * zC;
#pragma unroll
            for (int i = 0; i < 8; i++) {
                int row = bm + ((i >> 2) * 64) + ty * 4 + (i & 3);
#pragma unroll
                for (int jj = 0; jj < 2; jj++) {
                    int col = bn + jj * 64 + tx * 4;
#pragma unroll
                    for (int p = 0; p < 2; p++) {
                        int c2 = col + p * 2;
                        float b0 = 0.f, b1 = 0.f;
                        if (BIAS) { b0 = bias[c2]; b1 = bias[c2 + 1]; }
                        epi_store2<EPI>(acc[i][jj * 4 + p * 2] * scale + b0,
                                        acc[i][jj * 4 + p * 2 + 1] * scale + b1,
                                        row, c2, Cf, ldc, zCoff, Qf, Kf, Vf, Qh, Ql, Kh, Kl);
                    }
                }
            }
        }
    }
}

// ---------------------------------------------------------------------------
__global__ __launch_bounds__(256)
void split_hilo(const float4* __restrict__ in, __nv_bfloat162* __restrict__ oh,
                __nv_bfloat162* __restrict__ ol, size_t n4)
{
    size_t i = (size_t)blockIdx.x * blockDim.x + threadIdx.x;
    if (i >= n4) return;
    float4 v = in[i];
    __nv_bfloat162 h0 = __floats2bfloat162_rn(v.x, v.y);
    __nv_bfloat162 h1 = __floats2bfloat162_rn(v.z, v.w);
    __nv_bfloat162 l0 = __floats2bfloat162_rn(v.x - __bfloat162float(h0.x),
                                              v.y - __bfloat162float(h0.y));
    __nv_bfloat162 l1 = __floats2bfloat162_rn(v.z - __bfloat162float(h1.x),
                                              v.w - __bfloat162float(h1.y));
    oh[i * 2] = h0; oh[i * 2 + 1] = h1;
    ol[i * 2] = l0; ol[i * 2 + 1] = l1;
}

// Transpose Wq/Wk/Wv [D,H] -> Wtf [3H, D] fp32.
__global__ __launch_bounds__(256)
void transpose_w(const float* __restrict__ Wq, const float* __restrict__ Wk,
                 const float* __restrict__ Wv, float* __restrict__ out)
{
    __shared__ float tb[32][33];
    const int z = blockIdx.z;
    const float* in = z == 0 ? Wq : (z == 1 ? Wk : Wv);
    float* o = out + (size_t)z * HDIM * DIN;
    const int bx = blockIdx.x * 32, by = blockIdx.y * 32;
    const int tx = threadIdx.x & 31, ty = threadIdx.x >> 5;
#pragma unroll
    for (int j = 0; j < 4; j++) {
        int r = ty + j * 8;
        tb[r][tx] = in[(size_t)(by + r) * HDIM + bx + tx];
    }
    __syncthreads();
#pragma unroll
    for (int j = 0; j < 4; j++) {
        int r = ty + j * 8;
        o[(size_t)(bx + r) * DIN + by + tx] = tb[tx][r];
    }
}

// Transpose Vf [L,1024] per batch -> Vtf [1024, L].
__global__ __launch_bounds__(256)
void transpose_v(const float* __restrict__ Vf, float* __restrict__ out)
{
    __shared__ float tb[32][33];
    const int z = blockIdx.z;
    const float* in = Vf + (size_t)z * LSEQ * ODIM;
    float* o = out + (size_t)z * ODIM * LSEQ;
    const int bx = blockIdx.x * 32, by = blockIdx.y * 32;
    const int tx = threadIdx.x & 31, ty = threadIdx.x >> 5;
#pragma unroll
    for (int j = 0; j < 4; j++) {
        int r = ty + j * 8;
        tb[r][tx] = in[(size_t)(by + r) * ODIM + bx + tx];
    }
    __syncthreads();
#pragma unroll
    for (int j = 0; j < 4; j++) {
        int r = ty + j * 8;
        o[(size_t)(bx + r) * LSEQ + by + tx] = tb[tx][r];
    }
}

__global__ void concat_bias(const float* __restrict__ a, const float* __restrict__ b,
                            const float* __restrict__ c, float* __restrict__ o)
{
    int i = blockIdx.x * 256 + threadIdx.x;
    if (i < 1024) o[i] = a[i];
    else if (i < 2048) o[i] = b[i - 1024];
    else if (i < 3072) o[i] = c[i - 2048];
}

// Softmax over 2048 cols: writes normalized fp32 (in place) + bf16 hi/lo.
__global__ __launch_bounds__(256)
void softmax_norm(float* __restrict__ S, __nv_bfloat16* __restrict__ Sh,
                  __nv_bfloat16* __restrict__ Sl)
{
    const size_t row = blockIdx.x;
    float* p = S + row * (size_t)LSEQ;
    __nv_bfloat16* ph = Sh + row * (size_t)LSEQ;
    __nv_bfloat16* pl = Sl + row * (size_t)LSEQ;
    const int t = threadIdx.x;
    float v[8];
    float m = -1e30f;
#pragma unroll
    for (int i = 0; i < 8; i++) { v[i] = p[t + i * 256]; m = fmaxf(m, v[i]); }
    __shared__ float redm[8], reds[8];
#pragma unroll
    for (int o = 16; o > 0; o >>= 1) m = fmaxf(m, __shfl_xor_sync(0xFFFFFFFFu, m, o));
    if ((t & 31) == 0) redm[t >> 5] = m;
    __syncthreads();
    m = redm[0];
#pragma unroll
    for (int i = 1; i < 8; i++) m = fmaxf(m, redm[i]);
    float s = 0.0f;
#pragma unroll
    for (int i = 0; i < 8; i++) { v[i] = __expf(v[i] - m); s += v[i]; }
#pragma unroll
    for (int o = 16; o > 0; o >>= 1) s += __shfl_xor_sync(0xFFFFFFFFu, s, o);
    if ((t & 31) == 0) reds[t >> 5] = s;
    __syncthreads();
    s = reds[0];
#pragma unroll
    for (int i = 1; i < 8; i++) s += reds[i];
    const float inv = 1.0f / s;
#pragma unroll
    for (int i = 0; i < 8; i++) {
        float val = v[i] * inv;
        p[t + i * 256] = val;
        __nv_bfloat16 h = __float2bfloat16(val);
        ph[t + i * 256] = h;
        pl[t + i * 256] = __float2bfloat16(val - __bfloat162float(h));
    }
}

// ---------------------------------------------------------------------------
extern "C" void kernel_launch(void* const* d_in, const int* in_sizes, int n_in,
                              void* d_out, int out_size)
{
    const float* x  = (const float*)d_in[0];
    const float* Wq = (const float*)d_in[1];
    const float* bq = (const float*)d_in[2];
    const float* Wk = (const float*)d_in[3];
    const float* bk = (const float*)d_in[4];
    const float* Wv = (const float*)d_in[5];
    const float* bv = (const float*)d_in[6];
    float* out = (float*)d_out;

    __nv_bfloat16 *xh, *xl, *Wth, *Wtl, *Qh, *Ql, *Kh, *Kl, *Vth, *Vtl, *Sh, *Sl;
    float *Wtf, *bcat, *Qf, *Kf, *Vf, *Vtf, *S;
    cudaGetSymbolAddress((void**)&xh, g_xh);   cudaGetSymbolAddress((void**)&xl, g_xl);
    cudaGetSymbolAddress((void**)&Wtf, g_Wtf);
    cudaGetSymbolAddress((void**)&Wth, g_Wth); cudaGetSymbolAddress((void**)&Wtl, g_Wtl);
    cudaGetSymbolAddress((void**)&bcat, g_bcat);
    cudaGetSymbolAddress((void**)&Qf, g_Qf);   cudaGetSymbolAddress((void**)&Kf, g_Kf);
    cudaGetSymbolAddress((void**)&Vf, g_Vf);
    cudaGetSymbolAddress((void**)&Qh, g_Qh);   cudaGetSymbolAddress((void**)&Ql, g_Ql);
    cudaGetSymbolAddress((void**)&Kh, g_Kh);   cudaGetSymbolAddress((void**)&Kl, g_Kl);
    cudaGetSymbolAddress((void**)&Vtf, g_Vtf);
    cudaGetSymbolAddress((void**)&Vth, g_Vth); cudaGetSymbolAddress((void**)&Vtl, g_Vtl);
    cudaGetSymbolAddress((void**)&S, g_S);
    cudaGetSymbolAddress((void**)&Sh, g_Sh);   cudaGetSymbolAddress((void**)&Sl, g_Sl);

    cudaFuncSetAttribute(gemm_hybrid<1, true>,  cudaFuncAttributeMaxDynamicSharedMemorySize, SMEM_HYB);
    cudaFuncSetAttribute(gemm_hybrid<0, false>, cudaFuncAttributeMaxDynamicSharedMemorySize, SMEM_HYB);

    const int GRID = 2 * T_CTAS; // 296

    // 1) preps
    {
        size_t n4 = (size_t)MTOT * DIN / 4;
        split_hilo<<<(unsigned)((n4 + 255) / 256), 256>>>(
            (const float4*)x, (__nv_bfloat162*)xh, (__nv_bfloat162*)xl, n4);
    }
    transpose_w<<<dim3(HDIM / 32, DIN / 32, 3), 256>>>(Wq, Wk, Wv, Wtf);
    {
        size_t n4 = (size_t)NQKV * DIN / 4;
        split_hilo<<<(unsigned)((n4 + 255) / 256), 256>>>(
            (const float4*)Wtf, (__nv_bfloat162*)Wth, (__nv_bfloat162*)Wtl, n4);
    }
    concat_bias<<<12, 256>>>(bq, bk, bv, bcat);

    // 2) merged QKV projection (M=8192, N=3072, K=1024) -> Qf/Kf/Vf + Q/K limbs
    {
        int gx = NQKV / 128, gy = MTOT / 128, gz = 1;
        int nt = gx * gy * gz, ntT = nt * 7 / 10;
        gemm_hybrid<1, true><<<GRID, 256, SMEM_HYB>>>(
            x, xh, xl, Wtf, Wth, Wtl, bcat, 1.0f, DIN, DIN, DIN, 0, 0,
            nullptr, 0, 0, Qf, Kf, Vf, Qh, Ql, Kh, Kl, gx, gy, gz, ntT);
    }

    // 3) V transpose + split
    transpose_v<<<dim3(ODIM / 32, LSEQ / 32, NB), 256>>>(Vf, Vtf);
    {
        size_t n4 = (size_t)NB * ODIM * LSEQ / 4;
        split_hilo<<<(unsigned)((n4 + 255) / 256), 256>>>(
            (const float4*)Vtf, (__nv_bfloat162*)Vth, (__nv_bfloat162*)Vtl, n4);
    }

    // 4) S = (Q @ K^T)/sqrt(L), batched
    {
        int gx = LSEQ / 128, gy = LSEQ / 128, gz = NB;
        int nt = gx * gy * gz, ntT = nt * 7 / 10;
        gemm_hybrid<0, false><<<GRID, 256, SMEM_HYB>>>(
            Qf, Qh, Ql, Kf, Kh, Kl, nullptr, rsqrtf((float)LSEQ),
            HDIM, HDIM, HDIM,
            (size_t)LSEQ * HDIM, (size_t)LSEQ * HDIM,
            S, LSEQ, (size_t)LSEQ * LSEQ,
            nullptr, nullptr, nullptr, nullptr, nullptr, nullptr, nullptr,
            gx, gy, gz, ntT);
    }

    // 5) softmax (normalize in place + limbs)
    softmax_norm<<<NB * LSEQ, 256>>>(S, Sh, Sl);

    // 6) out = S @ Vt^T, batched
    {
        int gx = ODIM / 128, gy = LSEQ / 128, gz = NB;
        int nt = gx * gy * gz, ntT = nt * 7 / 10;
        gemm_hybrid<0, false><<<GRID, 256, SMEM_HYB>>>(
            S, Sh, Sl, Vtf, Vth, Vtl, nullptr, 1.0f,
            LSEQ, LSEQ, LSEQ,
            (size_t)LSEQ * LSEQ, (size_t)ODIM * LSEQ,
            out, ODIM, (size_t)LSEQ * ODIM,
            nullptr, nullptr, nullptr, nullptr, nullptr, nullptr, nullptr,
            gx, gy, gz, ntT);
    }
}

// round 7
// speedup vs baseline: 5.4814x; 4.4061x over previous
#include <cuda_runtime.h>
#include <cuda_fp16.h>
#include <cstdint>
#include <math.h>

static constexpr int NB = 4, LSEQ = 2048, DIN = 1024, HDIM = 1024, ODIM = 1024;
static constexpr int MTOT = NB * LSEQ; // 8192
static constexpr int NQKV = 3 * HDIM;  // 3072

// ---------------- scratch (__device__ globals) ------------------------------
__device__ __half g_x16[(size_t)MTOT * DIN];
__device__ __half g_Wt16[(size_t)NQKV * DIN];     // [3H, D]
__device__ float  g_bcat[NQKV];
__device__ __half g_Q16[(size_t)MTOT * HDIM];
__device__ __half g_K16[(size_t)MTOT * HDIM];
__device__ __half g_V16[(size_t)MTOT * ODIM];
__device__ __half g_Vt16[(size_t)NB * ODIM * LSEQ];
__device__ float  g_S[(size_t)NB * LSEQ * LSEQ];
__device__ __half g_S16[(size_t)NB * LSEQ * LSEQ];

// ---------------- PTX helpers ----------------------------------------------
__device__ __forceinline__ uint32_t smem_u32(const void* p) {
    uint32_t a;
    asm("{ .reg .u64 t; cvta.to.shared.u64 t, %1; cvt.u32.u64 %0, t; }" : "=r"(a) : "l"(p));
    return a;
}
#define CP16(dst, src) \
    asm volatile("cp.async.cg.shared.global [%0], [%1], 16;" :: "r"(dst), "l"(src))
#define CP_COMMIT() asm volatile("cp.async.commit_group;")
#define CP_WAIT1()  asm volatile("cp.async.wait_group 1;")
#define CP_WAIT0()  asm volatile("cp.async.wait_group 0;")
#define LDSM4(r, addr) \
    asm volatile("ldmatrix.sync.aligned.m8n8.x4.shared.b16 {%0,%1,%2,%3}, [%4];" \
        : "=r"((r)[0]), "=r"((r)[1]), "=r"((r)[2]), "=r"((r)[3]) : "r"(addr))
#define MMAF16(d, a, b0v, b1v) \
    asm volatile("mma.sync.aligned.m16n8k16.row.col.f32.f16.f16.f32 " \
        "{%0,%1,%2,%3}, {%4,%5,%6,%7}, {%8,%9}, {%0,%1,%2,%3};" \
        : "+f"((d)[0]), "+f"((d)[1]), "+f"((d)[2]), "+f"((d)[3]) \
        : "r"((a)[0]), "r"((a)[1]), "r"((a)[2]), "r"((a)[3]), "r"(b0v), "r"(b1v))

// ---------------- smem: A(128x32 f16, 80B pitch) + B same; 3 stages ---------
static constexpr uint32_t OPB = 10240;         // 128 rows * 80B
static constexpr uint32_t STG = 2 * OPB;       // 20480
static constexpr uint32_t SMEM_GEMM = 3 * STG; // 61440

// ---------------------------------------------------------------------------
// Single-pass fp16 GEMM: C[M,N] = scale*(A[M,K] @ B[N,K]^T) (+bias[col])
// CTA 128x128, BK=32, 8 warps (2x4 -> 64x32 warp tile), 3-stage cp.async,
// 2 CTAs/SM, persistent grid-stride over (gx,gy,gz).
// EPI 0: fp32 C.  EPI 1: fp16 QKV segment outputs.
// ---------------------------------------------------------------------------
template <bool BIAS, int EPI>
__global__ __launch_bounds__(256, 2)
void gemm_f16(const __half* __restrict__ A, const __half* __restrict__ B,
              const float* __restrict__ bias, float scale, int K, int lda, int ldb,
              size_t zA, size_t zB,
              float* __restrict__ Cf, int ldc, size_t zC,
              __half* __restrict__ Qo, __half* __restrict__ Ko, __half* __restrict__ Vo,
              int gx, int gy, int gz)
{
    extern __shared__ char smem[];
    const uint32_t sq = smem_u32(smem);
    const int t = threadIdx.x, lane = t & 31, wid = t >> 5;
    const int NST = K >> 5;
    const int m0w = (wid & 1) * 64, n0w = (wid >> 1) * 32;
    const uint32_t aoff = (uint32_t)((m0w + (lane & 15)) * 80 + (lane >> 4) * 16);
    const uint32_t boff = (uint32_t)((n0w + (lane & 15)) * 80 + (lane >> 4) * 16);
    const uint32_t dsto = (uint32_t)((t >> 2) * 80 + (t & 3) * 16);
    const int ntiles = gx * gy * gz;

    for (int tile = blockIdx.x; tile < ntiles; tile += gridDim.x) {
        const int bn = (tile % gx) * 128;
        const int tyz = tile / gx;
        const int bm = (tyz % gy) * 128;
        const int z = tyz / gy;

        const char* gA = (const char*)(A + (size_t)z * zA + (size_t)(bm + (t >> 2)) * lda + (t & 3) * 8);
        const char* gB = (const char*)(B + (size_t)z * zB + (size_t)(bn + (t >> 2)) * ldb + (t & 3) * 8);
        const size_t rA = (size_t)64 * lda * 2, rB = (size_t)64 * ldb * 2;

        auto issue = [&](int s) {
            const uint32_t sb = sq + (uint32_t)(s % 3) * STG;
            const size_t ko = (size_t)s * 64;  // 32 f16 = 64B per stage step
            CP16(sb + dsto,              gA + ko);
            CP16(sb + dsto + 5120,       gA + rA + ko);
            CP16(sb + OPB + dsto,        gB + ko);
            CP16(sb + OPB + dsto + 5120, gB + rB + ko);
        };

        float acc[4][4][4];
#pragma unroll
        for (int i = 0; i < 4; i++)
#pragma unroll
            for (int j = 0; j < 4; j++)
#pragma unroll
                for (int r = 0; r < 4; r++) acc[i][j][r] = 0.0f;

        issue(0); CP_COMMIT();
        issue(1); CP_COMMIT();

        for (int it = 0; it < NST; ++it) {
            CP_WAIT1();          // stage 'it' resident (FIFO; <=1 group outstanding)
            __syncthreads();     // all warps done reading stage being overwritten
            if (it + 2 < NST) issue(it + 2);
            CP_COMMIT();         // unconditional: keeps group count in sync

            const uint32_t sb = sq + (uint32_t)(it % 3) * STG;
#pragma unroll
            for (int s = 0; s < 2; ++s) {   // two k16 steps per 32-chunk
                uint32_t a[4][4], b[2][4];
#pragma unroll
                for (int tm = 0; tm < 4; ++tm)
                    LDSM4(a[tm], sb + aoff + tm * 1280u + s * 32u);
#pragma unroll
                for (int tn = 0; tn < 2; ++tn)
                    LDSM4(b[tn], sb + OPB + boff + tn * 1280u + s * 32u);
#pragma unroll
                for (int mi = 0; mi < 4; ++mi)
#pragma unroll
                    for (int ni = 0; ni < 4; ++ni)
                        MMAF16(acc[mi][ni], a[mi], b[ni >> 1][ni & 1], b[ni >> 1][2 + (ni & 1)]);
            }
        }
        __syncthreads();   // protect stages from next tile's prologue writes

        // ---- epilogue
        const int lr = lane >> 2, lc = (lane & 3) * 2;
#pragma unroll
        for (int mi = 0; mi < 4; ++mi) {
            const int r0 = bm + m0w + mi * 16 + lr;
#pragma unroll
            for (int ni = 0; ni < 4; ++ni) {
                const int col = bn + n0w + ni * 8 + lc;
                float b0 = 0.f, b1 = 0.f;
                if (BIAS) { b0 = bias[col]; b1 = bias[col + 1]; }
                float v00 = acc[mi][ni][0] * scale + b0, v01 = acc[mi][ni][1] * scale + b1;
                float v10 = acc[mi][ni][2] * scale + b0, v11 = acc[mi][ni][3] * scale + b1;
                if (EPI == 1) {
                    const int seg = col >> 10, lcol = col & 1023;
                    __half* O = seg == 0 ? Qo : (seg == 1 ? Ko : Vo);
                    const size_t o0 = (size_t)r0 * 1024 + lcol;
                    *(__half2*)(O + o0)               = __floats2half2_rn(v00, v01);
                    *(__half2*)(O + o0 + 8 * 1024)    = __floats2half2_rn(v10, v11);
                } else {
                    const size_t o0 = (size_t)z * zC + (size_t)r0 * ldc + col;
                    *(float2*)(Cf + o0)               = make_float2(v00, v01);
                    *(float2*)(Cf + o0 + (size_t)8 * ldc) = make_float2(v10, v11);
                }
            }
        }
    }
}

// ---------------------------------------------------------------------------
// fp32 -> fp16 elementwise (float4 -> half2 x2).
__global__ __launch_bounds__(256)
void to_f16(const float4* __restrict__ in, __half2* __restrict__ o, size_t n4)
{
    size_t i = (size_t)blockIdx.x * blockDim.x + threadIdx.x;
    if (i >= n4) return;
    float4 v = in[i];
    o[i * 2]     = __floats2half2_rn(v.x, v.y);
    o[i * 2 + 1] = __floats2half2_rn(v.z, v.w);
}

// Transpose Wq/Wk/Wv [D,H] fp32 -> Wt16 [3H,D] fp16.
__global__ __launch_bounds__(256)
void transpose_w16(const float* __restrict__ Wq, const float* __restrict__ Wk,
                   const float* __restrict__ Wv, __half* __restrict__ out)
{
    __shared__ float tb[32][33];
    const int z = blockIdx.z;
    const float* in = z == 0 ? Wq : (z == 1 ? Wk : Wv);
    __half* o = out + (size_t)z * HDIM * DIN;
    const int bx = blockIdx.x * 32, by = blockIdx.y * 32;
    const int tx = threadIdx.x & 31, ty = threadIdx.x >> 5;
#pragma unroll
    for (int j = 0; j < 4; j++) {
        int r = ty + j * 8;
        tb[r][tx] = in[(size_t)(by + r) * HDIM + bx + tx];
    }
    __syncthreads();
#pragma unroll
    for (int j = 0; j < 4; j++) {
        int r = ty + j * 8;
        o[(size_t)(bx + r) * DIN + by + tx] = __float2half_rn(tb[tx][r]);
    }
}

// Transpose V16 [L,1024] per batch -> Vt16 [1024, L] (fp16 in/out).
__global__ __launch_bounds__(256)
void transpose_v16(const __half* __restrict__ V, __half* __restrict__ out)
{
    __shared__ __half tb[32][34];
    const int z = blockIdx.z;
    const __half* in = V + (size_t)z * LSEQ * ODIM;
    __half* o = out + (size_t)z * ODIM * LSEQ;
    const int bx = blockIdx.x * 32, by = blockIdx.y * 32;
    const int tx = threadIdx.x & 31, ty = threadIdx.x >> 5;
#pragma unroll
    for (int j = 0; j < 4; j++) {
        int r = ty + j * 8;
        tb[r][tx] = in[(size_t)(by + r) * ODIM + bx + tx];
    }
    __syncthreads();
#pragma unroll
    for (int j = 0; j < 4; j++) {
        int r = ty + j * 8;
        o[(size_t)(bx + r) * LSEQ + by + tx] = tb[tx][r];
    }
}

__global__ void concat_bias(const float* __restrict__ a, const float* __restrict__ b,
                            const float* __restrict__ c, float* __restrict__ o)
{
    int i = blockIdx.x * 256 + threadIdx.x;
    if (i < 1024) o[i] = a[i];
    else if (i < 2048) o[i] = b[i - 1024];
    else if (i < 3072) o[i] = c[i - 2048];
}

// Row softmax over 2048 cols: fp32 in -> fp16 out.
__global__ __launch_bounds__(256)
void softmax_f16(const float* __restrict__ S, __half* __restrict__ So)
{
    const size_t row = blockIdx.x;
    const float* p = S + row * (size_t)LSEQ;
    __half* po = So + row * (size_t)LSEQ;
    const int t = threadIdx.x;
    float v[8];
    float m = -1e30f;
#pragma unroll
    for (int i = 0; i < 8; i++) { v[i] = p[t + i * 256]; m = fmaxf(m, v[i]); }
    __shared__ float redm[8], reds[8];
#pragma unroll
    for (int o = 16; o > 0; o >>= 1) m = fmaxf(m, __shfl_xor_sync(0xFFFFFFFFu, m, o));
    if ((t & 31) == 0) redm[t >> 5] = m;
    __syncthreads();
    m = redm[0];
#pragma unroll
    for (int i = 1; i < 8; i++) m = fmaxf(m, redm[i]);
    float s = 0.0f;
#pragma unroll
    for (int i = 0; i < 8; i++) { v[i] = __expf(v[i] - m); s += v[i]; }
#pragma unroll
    for (int o = 16; o > 0; o >>= 1) s += __shfl_xor_sync(0xFFFFFFFFu, s, o);
    if ((t & 31) == 0) reds[t >> 5] = s;
    __syncthreads();
    s = reds[0];
#pragma unroll
    for (int i = 1; i < 8; i++) s += reds[i];
    const float inv = 1.0f / s;
#pragma unroll
    for (int i = 0; i < 8; i++)
        po[t + i * 256] = __float2half_rn(v[i] * inv);
}

// ---------------------------------------------------------------------------
extern "C" void kernel_launch(void* const* d_in, const int* in_sizes, int n_in,
                              void* d_out, int out_size)
{
    const float* x  = (const float*)d_in[0];
    const float* Wq = (const float*)d_in[1];
    const float* bq = (const float*)d_in[2];
    const float* Wk = (const float*)d_in[3];
    const float* bk = (const float*)d_in[4];
    const float* Wv = (const float*)d_in[5];
    const float* bv = (const float*)d_in[6];
    float* out = (float*)d_out;

    __half *x16, *Wt16, *Q16, *K16, *V16, *Vt16, *S16;
    float *bcat, *S;
    cudaGetSymbolAddress((void**)&x16, g_x16);
    cudaGetSymbolAddress((void**)&Wt16, g_Wt16);
    cudaGetSymbolAddress((void**)&bcat, g_bcat);
    cudaGetSymbolAddress((void**)&Q16, g_Q16);
    cudaGetSymbolAddress((void**)&K16, g_K16);
    cudaGetSymbolAddress((void**)&V16, g_V16);
    cudaGetSymbolAddress((void**)&Vt16, g_Vt16);
    cudaGetSymbolAddress((void**)&S, g_S);
    cudaGetSymbolAddress((void**)&S16, g_S16);

    cudaFuncSetAttribute(gemm_f16<true, 1>,  cudaFuncAttributeMaxDynamicSharedMemorySize, SMEM_GEMM);
    cudaFuncSetAttribute(gemm_f16<false, 0>, cudaFuncAttributeMaxDynamicSharedMemorySize, SMEM_GEMM);

    const int PGRID = 296; // 2 CTAs/SM * 148 SMs

    // 1) preps
    {
        size_t n4 = (size_t)MTOT * DIN / 4;
        to_f16<<<(unsigned)((n4 + 255) / 256), 256>>>((const float4*)x, (__half2*)x16, n4);
    }
    transpose_w16<<<dim3(HDIM / 32, DIN / 32, 3), 256>>>(Wq, Wk, Wv, Wt16);
    concat_bias<<<12, 256>>>(bq, bk, bv, bcat);

    // 2) merged QKV projection (M=8192, N=3072, K=1024) -> Q16/K16/V16 fp16
    gemm_f16<true, 1><<<PGRID, 256, SMEM_GEMM>>>(
        x16, Wt16, bcat, 1.0f, DIN, DIN, DIN, 0, 0,
        nullptr, 0, 0, Q16, K16, V16,
        NQKV / 128, MTOT / 128, 1);

    // 3) V transpose per batch (fp16): [L,O] -> [O,L]
    transpose_v16<<<dim3(ODIM / 32, LSEQ / 32, NB), 256>>>(V16, Vt16);

    // 4) S = (Q @ K^T)/sqrt(L), batched, fp32 out
    gemm_f16<false, 0><<<PGRID, 256, SMEM_GEMM>>>(
        Q16, K16, nullptr, rsqrtf((float)LSEQ), HDIM, HDIM, HDIM,
        (size_t)LSEQ * HDIM, (size_t)LSEQ * HDIM,
        S, LSEQ, (size_t)LSEQ * LSEQ,
        nullptr, nullptr, nullptr,
        LSEQ / 128, LSEQ / 128, NB);

    // 5) softmax -> fp16 S
    softmax_f16<<<NB * LSEQ, 256>>>(S, S16);

    // 6) out = S @ V^T, batched, fp32 out
    gemm_f16<false, 0><<<PGRID, 256, SMEM_GEMM>>>(
        S16, Vt16, nullptr, 1.0f, LSEQ, LSEQ, LSEQ,
        (size_t)LSEQ * LSEQ, (size_t)ODIM * LSEQ,
        out, ODIM, (size_t)LSEQ * ODIM,
        nullptr, nullptr, nullptr,
        ODIM / 128, LSEQ / 128, NB);
}